// round 16
// baseline (speedup 1.0000x reference)
#include <cuda_runtime.h>
#include <math.h>

constexpr int Tt  = 2048;
constexpr int DHd = 512;
constexpr int NT  = 8 * 2048;
constexpr float SCALE = 0.044194173824159216f; // 512^-0.5

__device__ float g_q [NT * DHd];
__device__ float g_k [NT * DHd];
__device__ float g_v [NT * DHd];
__device__ float g_g [NT * DHd];
__device__ float g_Qc[NT * DHd];
__device__ float g_Qr[NT * DHd];
__device__ float g_Kr[NT * DHd];
__device__ float g_Qg[NT * DHd];
__device__ float g_Kg[NT * DHd];
__device__ float g_M [DHd * DHd];
__device__ float g_hist[8 * 32 * DHd];
__device__ float g_W [8 * 64 * 32];
__device__ float g_cos[Tt * 256];
__device__ float g_sin[Tt * 256];

// ---------------- GEMM (unchanged, at fp32 FFMA ceiling) ----------------
template<int MODE, int TRANSB, int SEL>
__global__ void gemm64(const float* __restrict__ Ain,
                       const float* __restrict__ Bin,
                       const float* __restrict__ bias) {
    const float* A;
    float* C;
    if constexpr (SEL == 0)      { A = Ain;  C = g_q;  }
    else if constexpr (SEL == 1) { A = Ain;  C = g_k;  }
    else if constexpr (SEL == 2) { A = Ain;  C = g_v;  }
    else if constexpr (SEL == 3) { A = Ain;  C = g_g;  }
    else if constexpr (SEL == 4) { A = g_Qr; C = g_Qg; }
    else                         { A = g_Kr; C = g_Kg; }
    const float* Bm = (SEL >= 4) ? (const float*)g_M : Bin;

    constexpr int K = 512, N = 512;
    __shared__ float As[16][68];
    __shared__ float Bs[16][68];
    const int t  = threadIdx.x;
    const int tx = t & 15, ty = t >> 4;
    const int n0 = blockIdx.x * 64, m0 = blockIdx.y * 64;
    const int ar = t >> 2, ac = (t & 3) << 2;
    float acc[4][4] = {};

    for (int k0 = 0; k0 < K; k0 += 16) {
        float4 va = *(const float4*)&A[(size_t)(m0 + ar) * K + k0 + ac];
        As[ac + 0][ar] = va.x; As[ac + 1][ar] = va.y;
        As[ac + 2][ar] = va.z; As[ac + 3][ar] = va.w;
        if constexpr (TRANSB) {
            float4 vb = *(const float4*)&Bm[(size_t)(n0 + ar) * K + k0 + ac];
            Bs[ac + 0][ar] = vb.x; Bs[ac + 1][ar] = vb.y;
            Bs[ac + 2][ar] = vb.z; Bs[ac + 3][ar] = vb.w;
        } else {
            *(float4*)&Bs[ty][tx << 2] =
                *(const float4*)&Bm[(size_t)(k0 + ty) * N + n0 + (tx << 2)];
        }
        __syncthreads();
        #pragma unroll
        for (int kk = 0; kk < 16; kk++) {
            float4 a4 = *(const float4*)&As[kk][ty << 2];
            float4 b4 = *(const float4*)&Bs[kk][tx << 2];
            float av[4] = {a4.x, a4.y, a4.z, a4.w};
            float bv[4] = {b4.x, b4.y, b4.z, b4.w};
            #pragma unroll
            for (int i = 0; i < 4; i++)
                #pragma unroll
                for (int j = 0; j < 4; j++)
                    acc[i][j] += av[i] * bv[j];
        }
        __syncthreads();
    }
    #pragma unroll
    for (int i = 0; i < 4; i++) {
        size_t rowb = (size_t)(m0 + (ty << 2) + i) * N;
        #pragma unroll
        for (int j = 0; j < 4; j++) {
            int n = n0 + (tx << 2) + j;
            float v = acc[i][j];
            if constexpr (MODE == 1) v = 1.f / (1.f + __expf(-(v + bias[n])));
            C[rowb + n] = v;
        }
    }
}

__global__ void rope_table() {
    int tp = blockIdx.x, p = threadIdx.x;
    double invf = pow(10000.0, -((double)(2 * p)) / 512.0);
    float ang = (float)tp * (float)invf;
    g_cos[tp * 256 + p] = (float)cos((double)ang);
    g_sin[tp * 256 + p] = (float)sin((double)ang);
}

__global__ void build_M(const float* __restrict__ A) {
    int idx = blockIdx.x * 256 + threadIdx.x;
    int d = idx >> 9, e = idx & 511;
    g_M[idx] = ((d == e) ? 1.f : 0.f) + A[idx] - A[(size_t)e * 512 + d];
}

// ---------------- recurrence (unchanged) ----------------
__global__ void chunk_scores(int i) {
    const int b = blockIdx.y;
    const int w = threadIdx.x >> 5, lane = threadIdx.x & 31;
    const int c = blockIdx.x * 8 + w;
    const float* krow = g_k + ((size_t)(b * Tt + i * 64 + c)) * 512;
    const float* hb = g_hist + (size_t)b * 32 * 512;
    __shared__ float sS[8][32];

    for (int j = 0; j < i; j += 2) {
        bool has1 = (j + 1 < i);
        const float* h0 = hb + (size_t)j * 512;
        const float* h1 = hb + (size_t)(j + 1) * 512;
        float a0 = 0.f, a1 = 0.f;
        for (int d = lane * 4; d < 512; d += 128) {
            float4 kv = *(const float4*)&krow[d];
            float4 v0 = *(const float4*)&h0[d];
            a0 += kv.x * v0.x + kv.y * v0.y + kv.z * v0.z + kv.w * v0.w;
            if (has1) {
                float4 v1 = *(const float4*)&h1[d];
                a1 += kv.x * v1.x + kv.y * v1.y + kv.z * v1.z + kv.w * v1.w;
            }
        }
        #pragma unroll
        for (int o = 16; o > 0; o >>= 1) {
            a0 += __shfl_xor_sync(0xffffffffu, a0, o);
            a1 += __shfl_xor_sync(0xffffffffu, a1, o);
        }
        if (lane == 0) {
            sS[w][j] = a0 * SCALE;
            if (has1) sS[w][j + 1] = a1 * SCALE;
        }
    }
    __syncwarp();
    float v = (lane < i) ? sS[w][lane] : -1e30f;
    float mx = v;
    #pragma unroll
    for (int o = 16; o > 0; o >>= 1) mx = fmaxf(mx, __shfl_xor_sync(0xffffffffu, mx, o));
    float e = (lane < i) ? __expf(v - mx) : 0.f;
    float s = e;
    #pragma unroll
    for (int o = 16; o > 0; o >>= 1) s += __shfl_xor_sync(0xffffffffu, s, o);
    if (lane < i) g_W[((size_t)b * 64 + c) * 32 + lane] = e / s;
}

__global__ void chunk_qout(int i) {
    const int b = blockIdx.y;
    const int d = blockIdx.x * 128 + threadIdx.x;
    __shared__ float sw[64][32];
    if (i > 0) {
        for (int idx = threadIdx.x; idx < 64 * 32; idx += 128)
            sw[idx >> 5][idx & 31] = g_W[(size_t)b * 2048 + idx];
        __syncthreads();
    }
    float qi_[64];
    #pragma unroll
    for (int c = 0; c < 64; c++) qi_[c] = 0.f;
    float base = 0.f;
    if (i > 0) {
        base = g_hist[((size_t)(b * 32 + i - 1)) * 512 + d];
        for (int j = 0; j < i; j++) {
            float h = g_hist[((size_t)(b * 32 + j)) * 512 + d];
            #pragma unroll
            for (int c = 0; c < 64; c++) qi_[c] += sw[c][j] * h;
        }
    }
    const size_t rb = ((size_t)(b * Tt + i * 64)) * 512 + d;
    float run = 0.f, val = 0.f;
    #pragma unroll
    for (int c = 0; c < 64; c++) {
        size_t idx = rb + (size_t)c * 512;
        run += g_g[idx] * g_q[idx];
        val = run + ((i > 0) ? (base + qi_[c]) : 0.f);
        g_Qc[idx] = val;
    }
    g_hist[((size_t)(b * 32 + i)) * 512 + d] = val;
}

// ---------------- norm + rope (unchanged) ----------------
__global__ void norm_rope() {
    const size_t row = blockIdx.x;
    const int tpos = (int)(row & 2047);
    const float* qc = g_Qc + row * 512;
    const float* kr = g_k + row * 512;
    __shared__ float red[8][4];
    __shared__ float stats[2];
    const int t = threadIdx.x;
    const int w = t >> 5, lane = t & 31;

    float a0 = qc[t], a1 = qc[t + 256];
    float c0 = kr[t], c1 = kr[t + 256];
    float sq = a0 + a1, sq2 = a0 * a0 + a1 * a1;
    float sk = c0 + c1, sk2 = c0 * c0 + c1 * c1;
    #pragma unroll
    for (int o = 16; o > 0; o >>= 1) {
        sq  += __shfl_xor_sync(0xffffffffu, sq,  o);
        sq2 += __shfl_xor_sync(0xffffffffu, sq2, o);
        sk  += __shfl_xor_sync(0xffffffffu, sk,  o);
        sk2 += __shfl_xor_sync(0xffffffffu, sk2, o);
    }
    if (lane == 0) { red[w][0] = sq; red[w][1] = sq2; red[w][2] = sk; red[w][3] = sk2; }
    __syncthreads();
    if (t == 0) {
        float A = 0, B2 = 0, C3 = 0, D4 = 0;
        #pragma unroll
        for (int ww = 0; ww < 8; ww++) {
            A += red[ww][0]; B2 += red[ww][1]; C3 += red[ww][2]; D4 += red[ww][3];
        }
        float mq = A / 512.f, mk = C3 / 512.f;
        float vq = (B2 - 512.f * mq * mq) / 511.f;
        float vk = (D4 - 512.f * mk * mk) / 511.f;
        float std_s = 0.5f * (sqrtf(fmaxf(vq, 0.f)) + sqrtf(fmaxf(vk, 0.f)));
        stats[0] = 0.5f * (mq + mk);
        stats[1] = 1.f / (std_s + 1e-6f);
    }
    __syncthreads();
    const float mean = stats[0], inv = stats[1];
    const float cs = g_cos[tpos * 256 + t];
    const float sn = g_sin[tpos * 256 + t];
    float q1 = (qc[2 * t]     - mean) * inv;
    float q2 = (qc[2 * t + 1] - mean) * inv;
    float k1 = (kr[2 * t]     - mean) * inv;
    float k2 = (kr[2 * t + 1] - mean) * inv;
    g_Qr[row * 512 + t]       = q1 * cs - q2 * sn;
    g_Qr[row * 512 + t + 256] = q1 * sn + q2 * cs;
    g_Kr[row * 512 + t]       = k1 * cs - k2 * sn;
    g_Kr[row * 512 + t + 256] = k1 * sn + k2 * cs;
}

// ---------------- Flash v3: 512 threads, register accumulator ----------------
// Thread (r = t>>3, dk = t&7) owns q-row r and d-cols dk*8..+7 of each chunk.
// smem: sQ[64][68] row-major, sK[64][68] swizzled K^T (reused as V), sS[64][68].
// K layout: element (k-row k, d dd) at  dd*68 + 4*((k>>3)^(dd&7)) + 32*((k>>2)&1) + (k&3)
// V layout: element (s, col c)     at  s*68  + 32*((c>>2)&1) + 4*(c>>3) + (c&3)
constexpr int F2_Q   = 0;
constexpr int F2_K   = 64 * 68;
constexpr int F2_S   = 2 * 64 * 68;
constexpr int F2_TOT = 3 * 64 * 68;       // 13056 floats = 52224 bytes

__global__ __launch_bounds__(512)
void flash2(const float* __restrict__ sinkp,
            const float* __restrict__ vnull,
            float* __restrict__ out) {
    extern __shared__ float sh[];
    float* sQ = sh + F2_Q;
    float* sK = sh + F2_K;
    float* sV = sh + F2_K;   // alias: V reuses K region in the PV phase
    float* sS = sh + F2_S;

    const int t  = threadIdx.x;
    const int r  = t >> 3;                  // own q-row 0..63
    const int dk = t & 7;                   // own col-group 0..7
    const int qi = 31 - (blockIdx.x >> 3);  // heavy tiles first (LPT)
    const int b  = blockIdx.x & 7;
    const int q0 = qi << 6;
    const size_t bT = (size_t)b * Tt;

    float acc[8][8];
    #pragma unroll
    for (int i = 0; i < 8; i++)
        #pragma unroll
        for (int j = 0; j < 8; j++) acc[i][j] = 0.f;
    float m = -1e30f, l = 0.f;

    for (int kb = 0; kb <= qi; kb++) {
        const int k0 = kb << 6;
        float sc[8] = {};
        // ---- S = Q K^T over d chunks of 64 ----
        for (int dc = 0; dc < 512; dc += 64) {
            #pragma unroll
            for (int ii = 0; ii < 2; ii++) {
                int i = t + ii * 512;
                int rr = i >> 4, c4 = (i & 15) << 2;
                *(float4*)&sQ[rr * 68 + c4] =
                    *(const float4*)&g_Qg[(bT + q0 + rr) * 512 + dc + c4];
                float4 kv = *(const float4*)&g_Kg[(bT + k0 + rr) * 512 + dc + c4];
                int ky = rr >> 3, kh = (rr >> 2) & 1, kb3 = rr & 3;
                int base = 32 * kh + kb3;
                sK[(c4 + 0) * 68 + 4 * (ky ^ ((c4 + 0) & 7)) + base] = kv.x;
                sK[(c4 + 1) * 68 + 4 * (ky ^ ((c4 + 1) & 7)) + base] = kv.y;
                sK[(c4 + 2) * 68 + 4 * (ky ^ ((c4 + 2) & 7)) + base] = kv.z;
                sK[(c4 + 3) * 68 + 4 * (ky ^ ((c4 + 3) & 7)) + base] = kv.w;
            }
            __syncthreads();
            #pragma unroll 8
            for (int dd = 0; dd < 64; dd++) {
                float qv = sQ[r * 68 + dd];
                int ko = dd * 68 + 4 * (dk ^ (dd & 7));
                float4 ka = *(const float4*)&sK[ko];
                float4 kc = *(const float4*)&sK[ko + 32];
                sc[0] += qv * ka.x; sc[1] += qv * ka.y;
                sc[2] += qv * ka.z; sc[3] += qv * ka.w;
                sc[4] += qv * kc.x; sc[5] += qv * kc.y;
                sc[6] += qv * kc.z; sc[7] += qv * kc.w;
            }
            __syncthreads();
        }
        // ---- mask + scale in regs, softmax via 8-lane shuffles ----
        const bool diag = (kb == qi);
        float p[8];
        float mx = -1e30f;
        #pragma unroll
        for (int j = 0; j < 8; j++) {
            float s = sc[j] * SCALE;
            if (diag && (dk * 8 + j) > r) s = -1e30f;
            p[j] = s;
            mx = fmaxf(mx, s);
        }
        mx = fmaxf(mx, __shfl_xor_sync(0xffffffffu, mx, 1));
        mx = fmaxf(mx, __shfl_xor_sync(0xffffffffu, mx, 2));
        mx = fmaxf(mx, __shfl_xor_sync(0xffffffffu, mx, 4));
        float mnew = fmaxf(m, mx);
        float al = __expf(m - mnew);
        float ls = 0.f;
        #pragma unroll
        for (int j = 0; j < 8; j++) {
            p[j] = __expf(p[j] - mnew);
            ls += p[j];
        }
        ls += __shfl_xor_sync(0xffffffffu, ls, 1);
        ls += __shfl_xor_sync(0xffffffffu, ls, 2);
        ls += __shfl_xor_sync(0xffffffffu, ls, 4);
        m = mnew;
        l = l * al + ls;
        *(float4*)&sS[r * 68 + dk * 8]     = make_float4(p[0], p[1], p[2], p[3]);
        *(float4*)&sS[r * 68 + dk * 8 + 4] = make_float4(p[4], p[5], p[6], p[7]);
        // rescale accumulator
        #pragma unroll
        for (int i = 0; i < 8; i++)
            #pragma unroll
            for (int j = 0; j < 8; j++) acc[i][j] *= al;
        // ---- O += P V, 8 d-chunks ----
        #pragma unroll
        for (int dcb = 0; dcb < 8; dcb++) {
            #pragma unroll
            for (int ii = 0; ii < 2; ii++) {
                int i = t + ii * 512;
                int rr = i >> 4, c4 = (i & 15) << 2;
                int g = c4 >> 3, h = (c4 >> 2) & 1;
                *(float4*)&sV[rr * 68 + 32 * h + 4 * g] =
                    *(const float4*)&g_v[(bT + k0 + rr) * 512 + dcb * 64 + c4];
            }
            __syncthreads();
            #pragma unroll 8
            for (int s = 0; s < 64; s++) {
                float pv = sS[r * 68 + s];
                int vo = s * 68 + 4 * dk;
                float4 v0 = *(const float4*)&sV[vo];
                float4 v1 = *(const float4*)&sV[vo + 32];
                acc[dcb][0] += pv * v0.x; acc[dcb][1] += pv * v0.y;
                acc[dcb][2] += pv * v0.z; acc[dcb][3] += pv * v0.w;
                acc[dcb][4] += pv * v1.x; acc[dcb][5] += pv * v1.y;
                acc[dcb][6] += pv * v1.z; acc[dcb][7] += pv * v1.w;
            }
            __syncthreads();
        }
    }
    // ---- epilogue: fold sink, normalize, write ----
    {
        const float skv = *sinkp;
        const float M2 = fmaxf(m, skv);
        const float em = __expf(m - M2);
        const float es = __expf(skv - M2);
        const float inv = 1.f / (l * em + es);
        const size_t ob = (bT + q0 + r) * (size_t)512;
        #pragma unroll
        for (int dcb = 0; dcb < 8; dcb++) {
            int d0 = dcb * 64 + dk * 8;
            float4 vn0 = *(const float4*)&vnull[d0];
            float4 vn1 = *(const float4*)&vnull[d0 + 4];
            float4 o0, o1;
            o0.x = (acc[dcb][0] * em + es * vn0.x) * inv;
            o0.y = (acc[dcb][1] * em + es * vn0.y) * inv;
            o0.z = (acc[dcb][2] * em + es * vn0.z) * inv;
            o0.w = (acc[dcb][3] * em + es * vn0.w) * inv;
            o1.x = (acc[dcb][4] * em + es * vn1.x) * inv;
            o1.y = (acc[dcb][5] * em + es * vn1.y) * inv;
            o1.z = (acc[dcb][6] * em + es * vn1.z) * inv;
            o1.w = (acc[dcb][7] * em + es * vn1.w) * inv;
            *(float4*)&out[ob + d0]     = o0;
            *(float4*)&out[ob + d0 + 4] = o1;
        }
    }
}

// ---------------- launch ----------------
extern "C" void kernel_launch(void* const* d_in, const int* in_sizes, int n_in,
                              void* d_out, int out_size) {
    const float* x     = (const float*)d_in[0];
    const float* Wq    = (const float*)d_in[1];
    const float* Wk    = (const float*)d_in[2];
    const float* Wv    = (const float*)d_in[3];
    const float* Wg    = (const float*)d_in[4];
    const float* bg    = (const float*)d_in[5];
    const float* A     = (const float*)d_in[6];
    const float* sink  = (const float*)d_in[7];
    const float* vnull = (const float*)d_in[8];
    float* out = (float*)d_out;

    cudaFuncSetAttribute(flash2,
                         cudaFuncAttributeMaxDynamicSharedMemorySize,
                         F2_TOT * (int)sizeof(float));

    dim3 gg(8, 256);
    gemm64<0, 1, 0><<<gg, 256>>>(x, Wq, nullptr);
    gemm64<0, 1, 1><<<gg, 256>>>(x, Wk, nullptr);
    gemm64<0, 1, 2><<<gg, 256>>>(x, Wv, nullptr);
    gemm64<1, 1, 3><<<gg, 256>>>(x, Wg, bg);

    rope_table<<<2048, 256>>>();
    build_M<<<1024, 256>>>(A);

    chunk_qout<<<dim3(4, 8), 128>>>(0);
    for (int i = 1; i < 32; i++) {
        chunk_scores<<<dim3(8, 8), 256>>>(i);
        chunk_qout<<<dim3(4, 8), 128>>>(i);
    }

    norm_rope<<<16384, 256>>>();

    gemm64<0, 0, 4><<<gg, 256>>>(nullptr, nullptr, nullptr);  // Qg = Qr @ M
    gemm64<0, 0, 5><<<gg, 256>>>(nullptr, nullptr, nullptr);  // Kg = Kr @ M

    flash2<<<256, 512, F2_TOT * (int)sizeof(float)>>>(sink, vnull, out);
}

// round 17
// speedup vs baseline: 1.3269x; 1.3269x over previous
#include <cuda_runtime.h>
#include <math.h>

constexpr int Tt  = 2048;
constexpr int DHd = 512;
constexpr int NT  = 8 * 2048;
constexpr float SCALE = 0.044194173824159216f; // 512^-0.5

typedef unsigned long long ull;

__device__ __forceinline__ ull pk2(float lo, float hi) {
    ull r; asm("mov.b64 %0, {%1, %2};" : "=l"(r) : "f"(lo), "f"(hi)); return r;
}
__device__ __forceinline__ void fma2(ull& d, ull a, ull b) {
    asm("fma.rn.f32x2 %0, %1, %2, %0;" : "+l"(d) : "l"(a), "l"(b));
}
__device__ __forceinline__ float2 up2(ull v) {
    float lo, hi; asm("mov.b64 {%0, %1}, %2;" : "=f"(lo), "=f"(hi) : "l"(v));
    return make_float2(lo, hi);
}

__device__ float g_q [NT * DHd];
__device__ float g_k [NT * DHd];
__device__ float g_v [NT * DHd];
__device__ float g_g [NT * DHd];
__device__ float g_Qc[NT * DHd];
__device__ float g_Qr[NT * DHd];
__device__ float g_Kr[NT * DHd];
__device__ float g_Qg[NT * DHd];
__device__ float g_Kg[NT * DHd];
__device__ float g_M [DHd * DHd];
__device__ float g_hist[8 * 32 * DHd];
__device__ float g_W [8 * 64 * 32];
__device__ float g_cos[Tt * 256];
__device__ float g_sin[Tt * 256];

// ---------------- GEMM: 128x128 tile, 8x8 microtile, FFMA2 (f32x2) ----------
// C[16384,512] = A @ B.  TRANSB=1: B is (512,512) weights (C=A*B^T);
// TRANSB=0: C = A*B.  MODE=1: sigmoid(C+bias).  BK=8, double-buffered.
template<int MODE, int TRANSB, int SEL>
__global__ __launch_bounds__(256, 2)
void gemm128(const float* __restrict__ Ain,
             const float* __restrict__ Bin,
             const float* __restrict__ bias) {
    const float* A;
    float* C;
    if constexpr (SEL == 0)      { A = Ain;  C = g_q;  }
    else if constexpr (SEL == 1) { A = Ain;  C = g_k;  }
    else if constexpr (SEL == 2) { A = Ain;  C = g_v;  }
    else if constexpr (SEL == 3) { A = Ain;  C = g_g;  }
    else if constexpr (SEL == 4) { A = g_Qr; C = g_Qg; }
    else                         { A = g_Kr; C = g_Kg; }
    const float* Bm = (SEL >= 4) ? (const float*)g_M : Bin;

    constexpr int K = 512, N = 512;
    __shared__ float As[2][8][132];
    __shared__ float Bs[2][8][132];
    const int t  = threadIdx.x;
    const int tx = t & 15, ty = t >> 4;          // 16x16 microtile grid
    const int m0 = blockIdx.y << 7, n0 = blockIdx.x << 7;
    const int sr = t >> 1, sk = (t & 1) << 2;    // transposed staging (A, B^T)
    const int bkr = t >> 5, bnc = (t & 31) << 2; // TRANSB=0 staging

    ull acc2[4][8];
    #pragma unroll
    for (int i = 0; i < 4; i++)
        #pragma unroll
        for (int j = 0; j < 8; j++) acc2[i][j] = 0ull;

    float4 va, vb;
    va = *(const float4*)&A[(size_t)(m0 + sr) * K + sk];
    if constexpr (TRANSB) vb = *(const float4*)&Bm[(size_t)(n0 + sr) * K + sk];
    else                  vb = *(const float4*)&Bm[(size_t)bkr * N + n0 + bnc];

    for (int kc = 0; kc < 64; kc++) {
        const int cur = kc & 1;
        As[cur][sk + 0][sr] = va.x; As[cur][sk + 1][sr] = va.y;
        As[cur][sk + 2][sr] = va.z; As[cur][sk + 3][sr] = va.w;
        if constexpr (TRANSB) {
            Bs[cur][sk + 0][sr] = vb.x; Bs[cur][sk + 1][sr] = vb.y;
            Bs[cur][sk + 2][sr] = vb.z; Bs[cur][sk + 3][sr] = vb.w;
        } else {
            *(float4*)&Bs[cur][bkr][bnc] = vb;
        }
        __syncthreads();
        if (kc < 63) {
            const int k0 = (kc + 1) << 3;
            va = *(const float4*)&A[(size_t)(m0 + sr) * K + k0 + sk];
            if constexpr (TRANSB)
                vb = *(const float4*)&Bm[(size_t)(n0 + sr) * K + k0 + sk];
            else
                vb = *(const float4*)&Bm[(size_t)(k0 + bkr) * N + n0 + bnc];
        }
        #pragma unroll
        for (int kk = 0; kk < 8; kk++) {
            // a-pairs: broadcast LDS.64 (address depends only on ty)
            ull av0 = *(const ull*)&As[cur][kk][(ty << 3) + 0];
            ull av1 = *(const ull*)&As[cur][kk][(ty << 3) + 2];
            ull av2 = *(const ull*)&As[cur][kk][(ty << 3) + 4];
            ull av3 = *(const ull*)&As[cur][kk][(ty << 3) + 6];
            float4 b0 = *(const float4*)&Bs[cur][kk][tx << 3];
            float4 b1 = *(const float4*)&Bs[cur][kk][(tx << 3) + 4];
            ull bd[8];
            bd[0] = pk2(b0.x, b0.x); bd[1] = pk2(b0.y, b0.y);
            bd[2] = pk2(b0.z, b0.z); bd[3] = pk2(b0.w, b0.w);
            bd[4] = pk2(b1.x, b1.x); bd[5] = pk2(b1.y, b1.y);
            bd[6] = pk2(b1.z, b1.z); bd[7] = pk2(b1.w, b1.w);
            #pragma unroll
            for (int j = 0; j < 8; j++) {
                fma2(acc2[0][j], av0, bd[j]);
                fma2(acc2[1][j], av1, bd[j]);
                fma2(acc2[2][j], av2, bd[j]);
                fma2(acc2[3][j], av3, bd[j]);
            }
        }
        __syncthreads();
    }

    // epilogue: unpack, optional sigmoid, coalesced float4 stores
    #pragma unroll
    for (int i2 = 0; i2 < 4; i2++) {
        float lo[8], hi[8];
        #pragma unroll
        for (int j = 0; j < 8; j++) {
            float2 v = up2(acc2[i2][j]);
            lo[j] = v.x; hi[j] = v.y;
        }
        if constexpr (MODE == 1) {
            #pragma unroll
            for (int j = 0; j < 8; j++) {
                float bb = bias[n0 + (tx << 3) + j];
                lo[j] = 1.f / (1.f + __expf(-(lo[j] + bb)));
                hi[j] = 1.f / (1.f + __expf(-(hi[j] + bb)));
            }
        }
        size_t r0 = (size_t)(m0 + (ty << 3) + (i2 << 1)) * N + n0 + (tx << 3);
        *(float4*)&C[r0]           = make_float4(lo[0], lo[1], lo[2], lo[3]);
        *(float4*)&C[r0 + 4]       = make_float4(lo[4], lo[5], lo[6], lo[7]);
        *(float4*)&C[r0 + N]       = make_float4(hi[0], hi[1], hi[2], hi[3]);
        *(float4*)&C[r0 + N + 4]   = make_float4(hi[4], hi[5], hi[6], hi[7]);
    }
}

__global__ void rope_table() {
    int tp = blockIdx.x, p = threadIdx.x;
    double invf = pow(10000.0, -((double)(2 * p)) / 512.0);
    float ang = (float)tp * (float)invf;
    g_cos[tp * 256 + p] = (float)cos((double)ang);
    g_sin[tp * 256 + p] = (float)sin((double)ang);
}

__global__ void build_M(const float* __restrict__ A) {
    int idx = blockIdx.x * 256 + threadIdx.x;
    int d = idx >> 9, e = idx & 511;
    g_M[idx] = ((d == e) ? 1.f : 0.f) + A[idx] - A[(size_t)e * 512 + d];
}

// ---------------- recurrence (unchanged) ----------------
__global__ void chunk_scores(int i) {
    const int b = blockIdx.y;
    const int w = threadIdx.x >> 5, lane = threadIdx.x & 31;
    const int c = blockIdx.x * 8 + w;
    const float* krow = g_k + ((size_t)(b * Tt + i * 64 + c)) * 512;
    const float* hb = g_hist + (size_t)b * 32 * 512;
    __shared__ float sS[8][32];

    for (int j = 0; j < i; j += 2) {
        bool has1 = (j + 1 < i);
        const float* h0 = hb + (size_t)j * 512;
        const float* h1 = hb + (size_t)(j + 1) * 512;
        float a0 = 0.f, a1 = 0.f;
        for (int d = lane * 4; d < 512; d += 128) {
            float4 kv = *(const float4*)&krow[d];
            float4 v0 = *(const float4*)&h0[d];
            a0 += kv.x * v0.x + kv.y * v0.y + kv.z * v0.z + kv.w * v0.w;
            if (has1) {
                float4 v1 = *(const float4*)&h1[d];
                a1 += kv.x * v1.x + kv.y * v1.y + kv.z * v1.z + kv.w * v1.w;
            }
        }
        #pragma unroll
        for (int o = 16; o > 0; o >>= 1) {
            a0 += __shfl_xor_sync(0xffffffffu, a0, o);
            a1 += __shfl_xor_sync(0xffffffffu, a1, o);
        }
        if (lane == 0) {
            sS[w][j] = a0 * SCALE;
            if (has1) sS[w][j + 1] = a1 * SCALE;
        }
    }
    __syncwarp();
    float v = (lane < i) ? sS[w][lane] : -1e30f;
    float mx = v;
    #pragma unroll
    for (int o = 16; o > 0; o >>= 1) mx = fmaxf(mx, __shfl_xor_sync(0xffffffffu, mx, o));
    float e = (lane < i) ? __expf(v - mx) : 0.f;
    float s = e;
    #pragma unroll
    for (int o = 16; o > 0; o >>= 1) s += __shfl_xor_sync(0xffffffffu, s, o);
    if (lane < i) g_W[((size_t)b * 64 + c) * 32 + lane] = e / s;
}

__global__ void chunk_qout(int i) {
    const int b = blockIdx.y;
    const int d = blockIdx.x * 128 + threadIdx.x;
    __shared__ float sw[64][32];
    if (i > 0) {
        for (int idx = threadIdx.x; idx < 64 * 32; idx += 128)
            sw[idx >> 5][idx & 31] = g_W[(size_t)b * 2048 + idx];
        __syncthreads();
    }
    float qi_[64];
    #pragma unroll
    for (int c = 0; c < 64; c++) qi_[c] = 0.f;
    float base = 0.f;
    if (i > 0) {
        base = g_hist[((size_t)(b * 32 + i - 1)) * 512 + d];
        for (int j = 0; j < i; j++) {
            float h = g_hist[((size_t)(b * 32 + j)) * 512 + d];
            #pragma unroll
            for (int c = 0; c < 64; c++) qi_[c] += sw[c][j] * h;
        }
    }
    const size_t rb = ((size_t)(b * Tt + i * 64)) * 512 + d;
    float run = 0.f, val = 0.f;
    #pragma unroll
    for (int c = 0; c < 64; c++) {
        size_t idx = rb + (size_t)c * 512;
        run += g_g[idx] * g_q[idx];
        val = run + ((i > 0) ? (base + qi_[c]) : 0.f);
        g_Qc[idx] = val;
    }
    g_hist[((size_t)(b * 32 + i)) * 512 + d] = val;
}

// ---------------- norm + rope (unchanged) ----------------
__global__ void norm_rope() {
    const size_t row = blockIdx.x;
    const int tpos = (int)(row & 2047);
    const float* qc = g_Qc + row * 512;
    const float* kr = g_k + row * 512;
    __shared__ float red[8][4];
    __shared__ float stats[2];
    const int t = threadIdx.x;
    const int w = t >> 5, lane = t & 31;

    float a0 = qc[t], a1 = qc[t + 256];
    float c0 = kr[t], c1 = kr[t + 256];
    float sq = a0 + a1, sq2 = a0 * a0 + a1 * a1;
    float sk = c0 + c1, sk2 = c0 * c0 + c1 * c1;
    #pragma unroll
    for (int o = 16; o > 0; o >>= 1) {
        sq  += __shfl_xor_sync(0xffffffffu, sq,  o);
        sq2 += __shfl_xor_sync(0xffffffffu, sq2, o);
        sk  += __shfl_xor_sync(0xffffffffu, sk,  o);
        sk2 += __shfl_xor_sync(0xffffffffu, sk2, o);
    }
    if (lane == 0) { red[w][0] = sq; red[w][1] = sq2; red[w][2] = sk; red[w][3] = sk2; }
    __syncthreads();
    if (t == 0) {
        float A = 0, B2 = 0, C3 = 0, D4 = 0;
        #pragma unroll
        for (int ww = 0; ww < 8; ww++) {
            A += red[ww][0]; B2 += red[ww][1]; C3 += red[ww][2]; D4 += red[ww][3];
        }
        float mq = A / 512.f, mk = C3 / 512.f;
        float vq = (B2 - 512.f * mq * mq) / 511.f;
        float vk = (D4 - 512.f * mk * mk) / 511.f;
        float std_s = 0.5f * (sqrtf(fmaxf(vq, 0.f)) + sqrtf(fmaxf(vk, 0.f)));
        stats[0] = 0.5f * (mq + mk);
        stats[1] = 1.f / (std_s + 1e-6f);
    }
    __syncthreads();
    const float mean = stats[0], inv = stats[1];
    const float cs = g_cos[tpos * 256 + t];
    const float sn = g_sin[tpos * 256 + t];
    float q1 = (qc[2 * t]     - mean) * inv;
    float q2 = (qc[2 * t + 1] - mean) * inv;
    float k1 = (kr[2 * t]     - mean) * inv;
    float k2 = (kr[2 * t + 1] - mean) * inv;
    g_Qr[row * 512 + t]       = q1 * cs - q2 * sn;
    g_Qr[row * 512 + t + 256] = q1 * sn + q2 * cs;
    g_Kr[row * 512 + t]       = k1 * cs - k2 * sn;
    g_Kr[row * 512 + t + 256] = k1 * sn + k2 * cs;
}

// ---------------- Flash attention: round-15 structure + FFMA2 inner loops ----
__device__ __forceinline__ int swz(int dd, int rgrp) {
    return dd * 68 + ((((rgrp) ^ (dd & 15) ^ (dd >> 4)) & 15) << 2);
}

constexpr int FSTR = 516;
constexpr int FQ   = 64 * FSTR;
constexpr int FK   = FQ + 64 * 68;
constexpr int FS   = FK + 64 * 68;
constexpr int FM   = FS + 64 * 68;
constexpr int FL   = FM + 64;
constexpr int FA   = FL + 64;
constexpr int FTOT = FA + 64;           // 46272 floats = 185088 bytes

__global__ __launch_bounds__(256)
void flash_kernel(const float* __restrict__ sinkp,
                  const float* __restrict__ vnull,
                  float* __restrict__ out) {
    extern __shared__ float sh[];
    float* sAcc = sh;
    float* sQt  = sh + FQ;
    float* sKt  = sh + FK;
    float* sSt  = sh + FS;
    float* sM   = sh + FM;
    float* sL   = sh + FL;
    float* sAl  = sh + FA;

    const int t  = threadIdx.x;
    const int tq = t >> 4, tk = t & 15;
    const int qi = 31 - (blockIdx.x >> 3);
    const int b  = blockIdx.x & 7;
    const int q0 = qi * 64;
    const size_t bT = (size_t)b * Tt;
    const int srow = t >> 4;
    const int sc4  = (t & 15) << 2;

    for (int f4 = t; f4 < FQ / 4; f4 += 256)
        ((float4*)sAcc)[f4] = make_float4(0.f, 0.f, 0.f, 0.f);
    if (t < 64) { sM[t] = -1e30f; sL[t] = 0.f; }
    __syncthreads();

    for (int kb = 0; kb <= qi; kb++) {
        const int k0 = kb * 64;
        ull sc2[4][2];
        #pragma unroll
        for (int i = 0; i < 4; i++) { sc2[i][0] = 0ull; sc2[i][1] = 0ull; }
        // ---- S = Q K^T over d in chunks of 64 (swizzled staging, FFMA2) ----
        for (int dc = 0; dc < 512; dc += 64) {
            #pragma unroll
            for (int rr = 0; rr < 4; rr++) {
                int r = srow + rr * 16;
                int rg = r >> 2, rb = r & 3;
                float4 qv = *(const float4*)&g_Qg[(bT + q0 + r) * 512 + dc + sc4];
                sQt[swz(sc4 + 0, rg) + rb] = qv.x;
                sQt[swz(sc4 + 1, rg) + rb] = qv.y;
                sQt[swz(sc4 + 2, rg) + rb] = qv.z;
                sQt[swz(sc4 + 3, rg) + rb] = qv.w;
                float4 kv = *(const float4*)&g_Kg[(bT + k0 + r) * 512 + dc + sc4];
                sKt[swz(sc4 + 0, rg) + rb] = kv.x;
                sKt[swz(sc4 + 1, rg) + rb] = kv.y;
                sKt[swz(sc4 + 2, rg) + rb] = kv.z;
                sKt[swz(sc4 + 3, rg) + rb] = kv.w;
            }
            __syncthreads();
            #pragma unroll
            for (int dd = 0; dd < 64; dd++) {
                float4 a4 = *(const float4*)&sQt[swz(dd, tq)];
                float4 b4 = *(const float4*)&sKt[swz(dd, tk)];
                ull bp0 = pk2(b4.x, b4.y);
                ull bp1 = pk2(b4.z, b4.w);
                ull ad0 = pk2(a4.x, a4.x);
                ull ad1 = pk2(a4.y, a4.y);
                ull ad2 = pk2(a4.z, a4.z);
                ull ad3 = pk2(a4.w, a4.w);
                fma2(sc2[0][0], ad0, bp0); fma2(sc2[0][1], ad0, bp1);
                fma2(sc2[1][0], ad1, bp0); fma2(sc2[1][1], ad1, bp1);
                fma2(sc2[2][0], ad2, bp0); fma2(sc2[2][1], ad2, bp1);
                fma2(sc2[3][0], ad3, bp0); fma2(sc2[3][1], ad3, bp1);
            }
            __syncthreads();
        }
        // ---- store S^T (swizzled) with scale + causal mask on diagonal ----
        const bool diag = (kb == qi);
        #pragma unroll
        for (int i = 0; i < 4; i++) {
            int r = (tq << 2) + i;
            float sv[4];
            float2 p0 = up2(sc2[i][0]);
            float2 p1 = up2(sc2[i][1]);
            sv[0] = p0.x; sv[1] = p0.y; sv[2] = p1.x; sv[3] = p1.y;
            #pragma unroll
            for (int j = 0; j < 4; j++) {
                int c = (tk << 2) + j;
                float s = sv[j] * SCALE;
                if (diag && c > r) s = -1e30f;
                sSt[swz(c, tq) + i] = s;
            }
        }
        __syncthreads();
        // ---- online softmax: 4 threads per row ----
        {
            int r = t >> 2, sub = t & 3;
            int rg = r >> 2, rb = r & 3;
            float mx = -1e30f;
            for (int c = sub; c < 64; c += 4) mx = fmaxf(mx, sSt[swz(c, rg) + rb]);
            mx = fmaxf(mx, __shfl_xor_sync(0xffffffffu, mx, 1));
            mx = fmaxf(mx, __shfl_xor_sync(0xffffffffu, mx, 2));
            float mold = sM[r];
            float mnew = fmaxf(mold, mx);
            float ls = 0.f;
            for (int c = sub; c < 64; c += 4) {
                float e = __expf(sSt[swz(c, rg) + rb] - mnew);
                sSt[swz(c, rg) + rb] = e;
                ls += e;
            }
            ls += __shfl_xor_sync(0xffffffffu, ls, 1);
            ls += __shfl_xor_sync(0xffffffffu, ls, 2);
            if (sub == 0) {
                float al = __expf(mold - mnew);
                sAl[r] = al;
                sM[r] = mnew;
                sL[r] = sL[r] * al + ls;
            }
        }
        __syncthreads();
        // ---- O = al*O + P V, d-chunked (FFMA2); V staged row-major in sKt ----
        for (int dc = 0; dc < 512; dc += 64) {
            #pragma unroll
            for (int rr = 0; rr < 4; rr++) {
                int r = srow + rr * 16;
                *(float4*)&sKt[r * 68 + sc4] =
                    *(const float4*)&g_v[(bT + k0 + r) * 512 + dc + sc4];
            }
            __syncthreads();
            ull o2[4][2];
            #pragma unroll
            for (int i = 0; i < 4; i++) { o2[i][0] = 0ull; o2[i][1] = 0ull; }
            #pragma unroll
            for (int s = 0; s < 64; s++) {
                float4 p4 = *(const float4*)&sSt[swz(s, tq)];
                float4 v4 = *(const float4*)&sKt[s * 68 + (tk << 2)];
                ull vp0 = pk2(v4.x, v4.y);
                ull vp1 = pk2(v4.z, v4.w);
                ull pd0 = pk2(p4.x, p4.x);
                ull pd1 = pk2(p4.y, p4.y);
                ull pd2 = pk2(p4.z, p4.z);
                ull pd3 = pk2(p4.w, p4.w);
                fma2(o2[0][0], pd0, vp0); fma2(o2[0][1], pd0, vp1);
                fma2(o2[1][0], pd1, vp0); fma2(o2[1][1], pd1, vp1);
                fma2(o2[2][0], pd2, vp0); fma2(o2[2][1], pd2, vp1);
                fma2(o2[3][0], pd3, vp0); fma2(o2[3][1], pd3, vp1);
            }
            #pragma unroll
            for (int i = 0; i < 4; i++) {
                int r = (tq << 2) + i;
                float al = sAl[r];
                float2 oa = up2(o2[i][0]);
                float2 ob = up2(o2[i][1]);
                float4* ap = (float4*)&sAcc[r * FSTR + dc + (tk << 2)];
                float4 a = *ap;
                a.x = a.x * al + oa.x;
                a.y = a.y * al + oa.y;
                a.z = a.z * al + ob.x;
                a.w = a.w * al + ob.y;
                *ap = a;
            }
            __syncthreads();
        }
    }
    // ---- epilogue: fold the sink logit, normalize, write ----
    {
        float skv = *sinkp;
        int r = t >> 2, sub = t & 3;
        float m = sM[r], l = sL[r];
        float M2 = fmaxf(m, skv);
        float em = __expf(m - M2);
        float es = __expf(skv - M2);
        float inv = 1.f / (l * em + es);
        size_t ob = (bT + q0 + r) * (size_t)512;
        for (int d = sub * 128; d < sub * 128 + 128; d += 4) {
            float4 a = *(float4*)&sAcc[r * FSTR + d];
            float4 vn = *(const float4*)&vnull[d];
            float4 o;
            o.x = (a.x * em + es * vn.x) * inv;
            o.y = (a.y * em + es * vn.y) * inv;
            o.z = (a.z * em + es * vn.z) * inv;
            o.w = (a.w * em + es * vn.w) * inv;
            *(float4*)&out[ob + d] = o;
        }
    }
}

// ---------------- launch ----------------
extern "C" void kernel_launch(void* const* d_in, const int* in_sizes, int n_in,
                              void* d_out, int out_size) {
    const float* x     = (const float*)d_in[0];
    const float* Wq    = (const float*)d_in[1];
    const float* Wk    = (const float*)d_in[2];
    const float* Wv    = (const float*)d_in[3];
    const float* Wg    = (const float*)d_in[4];
    const float* bg    = (const float*)d_in[5];
    const float* A     = (const float*)d_in[6];
    const float* sink  = (const float*)d_in[7];
    const float* vnull = (const float*)d_in[8];
    float* out = (float*)d_out;

    cudaFuncSetAttribute(flash_kernel,
                         cudaFuncAttributeMaxDynamicSharedMemorySize,
                         FTOT * (int)sizeof(float));

    dim3 gg(4, 128);
    gemm128<0, 1, 0><<<gg, 256>>>(x, Wq, nullptr);
    gemm128<0, 1, 1><<<gg, 256>>>(x, Wk, nullptr);
    gemm128<0, 1, 2><<<gg, 256>>>(x, Wv, nullptr);
    gemm128<1, 1, 3><<<gg, 256>>>(x, Wg, bg);

    rope_table<<<2048, 256>>>();
    build_M<<<1024, 256>>>(A);

    chunk_qout<<<dim3(4, 8), 128>>>(0);
    for (int i = 1; i < 32; i++) {
        chunk_scores<<<dim3(8, 8), 256>>>(i);
        chunk_qout<<<dim3(4, 8), 128>>>(i);
    }

    norm_rope<<<16384, 256>>>();

    gemm128<0, 0, 4><<<gg, 256>>>(nullptr, nullptr, nullptr);  // Qg = Qr @ M
    gemm128<0, 0, 5><<<gg, 256>>>(nullptr, nullptr, nullptr);  // Kg = Kr @ M

    flash_kernel<<<256, 256, FTOT * (int)sizeof(float)>>>(sink, vnull, out);
}